// round 5
// baseline (speedup 1.0000x reference)
#include <cuda_runtime.h>
#include <math.h>
#include <stdint.h>

// ---------------------------------------------------------------------------
// ImportanceRenderer, fused 3-kernel pipeline:
//  K0: transpose planes (B,3,32,256,256) -> channel-last (B,3,256,256,32)
//  K1: coarse eval (tri-plane bilinear + MLP) + fused importance sampling
//  K2: fine eval + fused merge-sort + final 96-sample ray march
// Block = 192 threads = 4 complete rays x 48 samples.
// ---------------------------------------------------------------------------

#define B_N 2
#define R_N 4096
#define SC 48
#define SF 48
#define NRAY (B_N * R_N)        // 8192
#define NSAMP (NRAY * SC)       // 393216
#define CPL 32
#define HPX 256
#define HID 64
#define CRGB 32
#define PLSTRIDE (HPX * HPX * CPL)   // 2097152 floats per plane (channel-last)

#define RAY_START_F 2.25f
#define DELTA_F (1.05f / 47.0f)

#define OFF_DEPTH (NRAY * CRGB)         // 262144
#define OFF_WSUM  (OFF_DEPTH + NRAY)    // 270336
#define OFF_SDF   (OFF_WSUM + NRAY)     // 278528

// Static scratch (no cudaMalloc allowed)
__device__ float g_planesT[6 * PLSTRIDE];           // 50.3 MB
__device__ float g_rgb_c[(size_t)NSAMP * CRGB];     // 50.3 MB
__device__ float g_zf[NSAMP];

__device__ __forceinline__ float softplus_f(float x) {
    // max(x,0) + log1p(exp(-|x|)), fast-math flavor
    return fmaxf(x, 0.f) + __logf(1.f + __expf(-fabsf(x)));
}
__device__ __forceinline__ float sigmoid_f(float x) {
    return 1.f / (1.f + __expf(-x));
}
__device__ __forceinline__ float zc_depth(int i) {
    return RAY_START_F + ((float)i + 0.5f) * DELTA_F;
}

// ---------------------------------------------------------------------------
// K0: tiled transpose (C=32) x (HW) -> (HW) x (C), per plane
// ---------------------------------------------------------------------------
__global__ void transpose_planes_kernel(const float* __restrict__ in) {
    __shared__ float tile[32][33];
    int p = blockIdx.y;
    int hw0 = blockIdx.x * 32;
    int tx = threadIdx.x;
    int ty = threadIdx.y;
    const float* ip = in + (size_t)p * CPL * (HPX * HPX);
    float* op = g_planesT + (size_t)p * PLSTRIDE;
    #pragma unroll
    for (int c = ty; c < 32; c += 8)
        tile[c][tx] = ip[(size_t)c * (HPX * HPX) + hw0 + tx];
    __syncthreads();
    #pragma unroll
    for (int r = ty; r < 32; r += 8)
        op[(size_t)(hw0 + r) * 32 + tx] = tile[tx][r];
}

// ---------------------------------------------------------------------------
// K1/K2: fused eval. PASS=0 coarse (+importance), PASS=1 fine (+finalize).
// ---------------------------------------------------------------------------
template <int PASS>
__global__ __launch_bounds__(192)
void eval_kernel(const float* __restrict__ origins,
                 const float* __restrict__ dirs,
                 const float* __restrict__ w1, const float* __restrict__ b1,
                 const float* __restrict__ w2, const float* __restrict__ b2,
                 float* __restrict__ out) {
    __shared__ __align__(16) float s_w1t[HID * CPL];   // [j][c]
    __shared__ __align__(16) float s_w2[HID * 36];     // [j][k] padded to 36
    __shared__ float s_b1[HID];
    __shared__ float s_b2[36];
    __shared__ __align__(16) float s_feat[192 * 36];   // feat, later rgb
    __shared__ float s_sig[192];
    __shared__ float s_z[192];

    const int tid = threadIdx.x;
    const int lane = tid & 31;
    const int warp = tid >> 5;
    const unsigned FULL = 0xffffffffu;

    // ---- load MLP weights ----
    for (int i = tid; i < HID * CPL; i += 192) {
        int j = i >> 5, c = i & 31;
        s_w1t[i] = w1[c * HID + j];
    }
    for (int i = tid; i < HID * 36; i += 192) {
        int j = i / 36, k = i - j * 36;
        s_w2[i] = (k < 33) ? w2[j * 33 + k] : 0.f;
    }
    if (tid < HID) s_b1[tid] = b1[tid];
    if (tid < 36) s_b2[tid] = (tid < 33) ? b2[tid] : 0.f;

    // ---- phase A: per-thread coord + bilinear setup for its own sample ----
    const int gs = blockIdx.x * 192 + tid;
    const int rayLocal = tid / 48;
    const int samp = tid - rayLocal * 48;
    const int ray = blockIdx.x * 4 + rayLocal;

    float t;
    if (PASS == 0) t = zc_depth(samp);
    else t = __ldg(&g_zf[gs]);
    s_z[tid] = t;

    float ox = __ldg(&origins[ray * 3 + 0]);
    float oy = __ldg(&origins[ray * 3 + 1]);
    float oz = __ldg(&origins[ray * 3 + 2]);
    float dx = __ldg(&dirs[ray * 3 + 0]);
    float dy = __ldg(&dirs[ray * 3 + 1]);
    float dz = __ldg(&dirs[ray * 3 + 2]);
    float X = fmaf(t, dx, ox), Y = fmaf(t, dy, oy), Z = fmaf(t, dz, oz);
    int bb = ray >> 12;

    // plane0:(X,Y)  plane1:(X,Z)  plane2:(Z,X)
    float us0 = X, us1 = X, us2 = Z;
    float vs0 = Y, vs1 = Z, vs2 = X;

    int oy0[3], oy1[3], xp[3];
    float wx0[3], wx1[3], wy0[3], wy1[3];
    #pragma unroll
    for (int p = 0; p < 3; p++) {
        float u = (p == 0) ? us0 : (p == 1) ? us1 : us2;
        float v = (p == 0) ? vs0 : (p == 1) ? vs1 : vs2;
        float x = fmaf(u, 128.f, 127.5f);     // ((u+1)*256-1)*0.5
        float y = fmaf(v, 128.f, 127.5f);
        float x0f = floorf(x), y0f = floorf(y);
        float fx = x - x0f, fy = y - y0f;
        int xi0 = min(max((int)x0f, 0), 255);
        int xi1 = min(max((int)x0f + 1, 0), 255);
        int yi0 = min(max((int)y0f, 0), 255);
        int yi1 = min(max((int)y0f + 1, 0), 255);
        wx0[p] = (x0f >= 0.f && x0f < 256.f) ? (1.f - fx) : 0.f;
        wx1[p] = (x0f + 1.f >= 0.f && x0f + 1.f < 256.f) ? fx : 0.f;
        wy0[p] = (y0f >= 0.f && y0f < 256.f) ? (1.f - fy) : 0.f;
        wy1[p] = (y0f + 1.f >= 0.f && y0f + 1.f < 256.f) ? fy : 0.f;
        int base = (bb * 3 + p) * PLSTRIDE;
        oy0[p] = base + yi0 * (HPX * CPL);
        oy1[p] = base + yi1 * (HPX * CPL);
        xp[p] = (xi0 * CPL) | ((xi1 * CPL) << 16);
    }

    // ---- gather phase: warp-cooperative, lane = corner(2b) x chunk(3b) ----
    const int cx = lane >> 3 & 1;     // corner x-bit
    const int cy = lane >> 4;         // corner y-bit
    const int chunk = lane & 7;
    for (int i = 0; i < 32; i++) {
        int s = (warp << 5) + i;
        float ax = 0.f, ay = 0.f, az = 0.f, aw = 0.f;
        #pragma unroll
        for (int p = 0; p < 3; p++) {
            int o0 = __shfl_sync(FULL, oy0[p], i);
            int o1 = __shfl_sync(FULL, oy1[p], i);
            int xx = __shfl_sync(FULL, xp[p], i);
            float wwx0 = __shfl_sync(FULL, wx0[p], i);
            float wwx1 = __shfl_sync(FULL, wx1[p], i);
            float wwy0 = __shfl_sync(FULL, wy0[p], i);
            float wwy1 = __shfl_sync(FULL, wy1[p], i);
            int off = (cy ? o1 : o0) + (cx ? (xx >> 16) : (xx & 0xffff));
            float w = (cx ? wwx1 : wwx0) * (cy ? wwy1 : wwy0);
            float4 v = __ldg(reinterpret_cast<const float4*>(g_planesT + off) + chunk);
            ax = fmaf(v.x, w, ax);
            ay = fmaf(v.y, w, ay);
            az = fmaf(v.z, w, az);
            aw = fmaf(v.w, w, aw);
        }
        // butterfly-reduce over the 4 corner groups
        ax += __shfl_xor_sync(FULL, ax, 8);
        ay += __shfl_xor_sync(FULL, ay, 8);
        az += __shfl_xor_sync(FULL, az, 8);
        aw += __shfl_xor_sync(FULL, aw, 8);
        ax += __shfl_xor_sync(FULL, ax, 16);
        ay += __shfl_xor_sync(FULL, ay, 16);
        az += __shfl_xor_sync(FULL, az, 16);
        aw += __shfl_xor_sync(FULL, aw, 16);
        if (lane < 8) {
            const float k3 = 1.f / 3.f;
            float4 r = make_float4(ax * k3, ay * k3, az * k3, aw * k3);
            *(reinterpret_cast<float4*>(s_feat + s * 36) + chunk) = r;
        }
    }
    __syncthreads();

    // ---- MLP phase: thread = sample ----
    float feat[CPL];
    {
        const float4* f4 = reinterpret_cast<const float4*>(s_feat + tid * 36);
        #pragma unroll
        for (int k = 0; k < 8; k++) {
            float4 v = f4[k];
            feat[4 * k + 0] = v.x; feat[4 * k + 1] = v.y;
            feat[4 * k + 2] = v.z; feat[4 * k + 3] = v.w;
        }
    }
    float acc[36];
    #pragma unroll
    for (int k = 0; k < 36; k++) acc[k] = s_b2[k];
    const float4* w1t4 = reinterpret_cast<const float4*>(s_w1t);
    const float4* w24 = reinterpret_cast<const float4*>(s_w2);
    for (int j = 0; j < HID; j++) {
        float h = s_b1[j];
        #pragma unroll
        for (int cc = 0; cc < 8; cc++) {
            float4 wv = w1t4[j * 8 + cc];
            h = fmaf(feat[4 * cc + 0], wv.x, h);
            h = fmaf(feat[4 * cc + 1], wv.y, h);
            h = fmaf(feat[4 * cc + 2], wv.z, h);
            h = fmaf(feat[4 * cc + 3], wv.w, h);
        }
        h = softplus_f(h);
        #pragma unroll
        for (int kk = 0; kk < 9; kk++) {
            float4 wv = w24[j * 9 + kk];
            acc[4 * kk + 0] = fmaf(h, wv.x, acc[4 * kk + 0]);
            acc[4 * kk + 1] = fmaf(h, wv.y, acc[4 * kk + 1]);
            acc[4 * kk + 2] = fmaf(h, wv.z, acc[4 * kk + 2]);
            acc[4 * kk + 3] = fmaf(h, wv.w, acc[4 * kk + 3]);
        }
    }
    s_sig[tid] = acc[0];
    if (PASS == 0) out[OFF_SDF + gs] = acc[0];

    // rgb -> own row of s_feat (no cross-thread hazard: each thread its row)
    #pragma unroll
    for (int k = 0; k < CRGB; k++)
        s_feat[tid * 36 + k] = sigmoid_f(acc[1 + k]) * 1.002f - 0.001f;
    __syncthreads();

    if (PASS == 0) {
        // ---- coalesced rgb_c store ----
        size_t ob = (size_t)blockIdx.x * 192 * CRGB;
        for (int i = tid; i < 192 * CRGB; i += 192) {
            int sm = i >> 5, k = i & 31;
            g_rgb_c[ob + i] = s_feat[sm * 36 + k];
        }
        // ---- fused importance sampling: thread r handles ray r (r<4) ----
        if (tid < 4) {
            const float* sg = s_sig + tid * SC;
            int rayO = blockIdx.x * 4 + tid;
            float w[SC - 1];
            float T = 1.f;
            float prev = sg[0];
            for (int i = 0; i < SC - 1; i++) {
                float cur = sg[i + 1];
                float dens = softplus_f(0.5f * (prev + cur) - 1.f);
                float a = 1.f - __expf(-dens * DELTA_F);
                w[i] = a * T;
                T *= (1.f - a + 1e-10f);
                prev = cur;
            }
            float pw[45];
            float sum = 0.f;
            for (int i = 1; i <= 45; i++) {
                float wp_i = w[i - 1];
                float wp_i1 = w[i];
                float wp_i2 = (i + 2 <= 47) ? w[i + 1] : 0.f;
                float wm0 = fmaxf(wp_i, wp_i1);
                float wm1 = fmaxf(wp_i1, wp_i2);
                float val = 0.5f * (wm0 + wm1) + 0.01f;
                pw[i - 1] = val;
                sum += val;
            }
            float cdf[46];
            cdf[0] = 0.f;
            for (int i = 0; i < 45; i++) cdf[i + 1] = cdf[i] + pw[i] / sum;
            int idx = 0;
            for (int j = 0; j < SF; j++) {
                float u = (float)j / 47.0f;
                while (idx < 46 && cdf[idx] <= u) idx++;
                int below = idx - 1;
                below = below < 0 ? 0 : (below > 45 ? 45 : below);
                int above = idx > 45 ? 45 : idx;
                float cb = cdf[below], ca = cdf[above];
                float bbv = 0.5f * (zc_depth(below) + zc_depth(below + 1));
                float bav = 0.5f * (zc_depth(above) + zc_depth(above + 1));
                float d = ca - cb;
                float denom = (d < 1e-5f) ? 1.f : d;
                g_zf[(size_t)rayO * SF + j] = bbv + (u - cb) / denom * (bav - bbv);
            }
        }
    } else {
        // ---- fused merge + final ray march: warp wp handles ray wp (<4) ----
        if (warp < 4) {
            int rayO = blockIdx.x * 4 + warp;
            const float* sdfc = out + OFF_SDF + (size_t)rayO * SC;
            const float* zf = s_z + warp * SF;
            const float* sf = s_sig + warp * SF;
            int ic = 0, ifn = 0;
            float T = 1.f, rgb_acc = 0.f, dep = 0.f, ws = 0.f;
            float zp, sp2, cp;
            {
                bool tc = (zc_depth(0) <= zf[0]);
                if (tc) {
                    zp = zc_depth(0); sp2 = __ldg(&sdfc[0]);
                    cp = __ldg(&g_rgb_c[((size_t)rayO * SC) * CRGB + lane]);
                    ic = 1;
                } else {
                    zp = zf[0]; sp2 = sf[0];
                    cp = s_feat[(warp * SF) * 36 + lane];
                    ifn = 1;
                }
            }
            for (int i = 1; i < SC + SF; i++) {
                bool tc = (ic < SC) && (ifn >= SF || zc_depth(ic) <= zf[ifn]);
                float z, sgv, cc;
                if (tc) {
                    z = zc_depth(ic); sgv = __ldg(&sdfc[ic]);
                    cc = __ldg(&g_rgb_c[((size_t)rayO * SC + ic) * CRGB + lane]);
                    ic++;
                } else {
                    z = zf[ifn]; sgv = sf[ifn];
                    cc = s_feat[(warp * SF + ifn) * 36 + lane];
                    ifn++;
                }
                float delta = z - zp;
                float cmid = 0.5f * (cp + cc);
                float smid = softplus_f(0.5f * (sp2 + sgv) - 1.f);
                float a = 1.f - __expf(-smid * delta);
                float wgt = a * T;
                T *= (1.f - a + 1e-10f);
                rgb_acc = fmaf(wgt, cmid, rgb_acc);
                dep = fmaf(wgt, 0.5f * (zp + z), dep);
                ws += wgt;
                zp = z; sp2 = sgv; cp = cc;
            }
            out[(size_t)rayO * CRGB + lane] = rgb_acc * 2.f - 1.f;
            if (lane == 0) {
                out[OFF_DEPTH + rayO] = dep;
                out[OFF_WSUM + rayO] = ws;
            }
        }
    }
}

// ---------------------------------------------------------------------------
extern "C" void kernel_launch(void* const* d_in, const int* in_sizes, int n_in,
                              void* d_out, int out_size) {
    const float* planes = (const float*)d_in[0];
    const float* org    = (const float*)d_in[1];
    const float* dir    = (const float*)d_in[2];
    const float* w1     = (const float*)d_in[3];
    const float* b1     = (const float*)d_in[4];
    const float* w2     = (const float*)d_in[5];
    const float* b2     = (const float*)d_in[6];
    float* out = (float*)d_out;

    {
        dim3 tb(32, 8), tg(HPX * HPX / 32, 6);
        transpose_planes_kernel<<<tg, tb>>>(planes);
    }
    eval_kernel<0><<<NRAY / 4, 192>>>(org, dir, w1, b1, w2, b2, out);
    eval_kernel<1><<<NRAY / 4, 192>>>(org, dir, w1, b1, w2, b2, out);
}